// round 15
// baseline (speedup 1.0000x reference)
#include <cuda_runtime.h>
#include <cuda_fp16.h>
#include <cstdint>

#define NN     50000
#define EE     800000
#define F_IN   128
#define F_HID  256
#define F_OUT  128

#define SCAN_T   256
#define NSTRIP   ((NN + SCAN_T - 1) / SCAN_T)   // 196

// Scratch (__device__ globals; never materialized as host pointers)
__device__ __align__(16) int    g_cnt     [NN];
__device__ __align__(16) int    g_rowstart[NN + 1];
__device__ __align__(16) int    g_cursor  [NN];
__device__ __align__(16) int    g_adj     [EE];
__device__ __align__(16) int    g_ssum    [NSTRIP];
__device__ __align__(16) int    g_soff    [NSTRIP];
__device__ __align__(16) float  g_dinv    [NN];
__device__ __align__(16) __half g_xh      [(size_t)NN * F_IN];   // fp16 copy of x
__device__ __align__(16) __half g_h2h     [(size_t)NN * F_OUT];  // a1 @ W2 (fp16)
__device__ __align__(16) float  g_agg1    [(size_t)NN * F_IN];   // A_norm @ x
__device__ __align__(16) float  g_a1      [(size_t)NN * F_HID];  // relu(agg1 @ W1 + b1)

// ---------------------------------------------------------------------------
// CSR build
// ---------------------------------------------------------------------------
__global__ void zero_cnt_k() {
    int i = blockIdx.x * blockDim.x + threadIdx.x;
    if (i < NN) g_cnt[i] = 0;
}

__global__ void cnt_k(const int* __restrict__ dst) {
    int e = blockIdx.x * blockDim.x + threadIdx.x;
    if (e < EE) atomicAdd(&g_cnt[dst[e]], 1);
}

// x (fp32) -> g_xh (fp16), 8 elems/thread
__global__ void cvt_x_k(const float* __restrict__ x) {
    int i = blockIdx.x * blockDim.x + threadIdx.x;   // i over NN*F_IN/8
    if (i < NN * F_IN / 8) {
        const float4* xp = (const float4*)x + 2 * i;
        float4 a = xp[0], b = xp[1];
        __half2* hp = (__half2*)g_xh + 4 * i;
        hp[0] = __floats2half2_rn(a.x, a.y);
        hp[1] = __floats2half2_rn(a.z, a.w);
        hp[2] = __floats2half2_rn(b.x, b.y);
        hp[3] = __floats2half2_rn(b.z, b.w);
    }
}

__global__ void strip_sum_k() {
    __shared__ int sh[SCAN_T];
    int gid = blockIdx.x * SCAN_T + threadIdx.x;
    sh[threadIdx.x] = (gid < NN) ? g_cnt[gid] : 0;
    __syncthreads();
    for (int o = SCAN_T / 2; o > 0; o >>= 1) {
        if (threadIdx.x < o) sh[threadIdx.x] += sh[threadIdx.x + o];
        __syncthreads();
    }
    if (threadIdx.x == 0) g_ssum[blockIdx.x] = sh[0];
}

__global__ void scan_strips_k() {
    int tid  = threadIdx.x;
    int lane = tid & 31, warp = tid >> 5;
    int v = (tid < NSTRIP) ? g_ssum[tid] : 0;
    int incl = v;
    #pragma unroll
    for (int o = 1; o < 32; o <<= 1) {
        int t = __shfl_up_sync(0xFFFFFFFFu, incl, o);
        if (lane >= o) incl += t;
    }
    __shared__ int wsum[8];
    if (lane == 31) wsum[warp] = incl;
    __syncthreads();
    if (warp == 0 && lane < 8) {
        int w = wsum[lane];
        #pragma unroll
        for (int o = 1; o < 8; o <<= 1) {
            int t = __shfl_up_sync(0xFFu, w, o);
            if (lane >= o) w += t;
        }
        wsum[lane] = w;
    }
    __syncthreads();
    int total_incl = incl + (warp ? wsum[warp - 1] : 0);
    if (tid < NSTRIP) g_soff[tid] = total_incl - v;
    if (tid == SCAN_T - 1) g_rowstart[NN] = total_incl;   // == EE
}

// per-strip exclusive scan + global offset; also computes dinv
__global__ void rowstart_k() {
    int tid  = threadIdx.x;
    int gid  = blockIdx.x * SCAN_T + tid;
    int lane = tid & 31, warp = tid >> 5;
    int v = (gid < NN) ? g_cnt[gid] : 0;
    int incl = v;
    #pragma unroll
    for (int o = 1; o < 32; o <<= 1) {
        int t = __shfl_up_sync(0xFFFFFFFFu, incl, o);
        if (lane >= o) incl += t;
    }
    __shared__ int wsum[8];
    if (lane == 31) wsum[warp] = incl;
    __syncthreads();
    if (warp == 0 && lane < 8) {
        int w = wsum[lane];
        #pragma unroll
        for (int o = 1; o < 8; o <<= 1) {
            int t = __shfl_up_sync(0xFFu, w, o);
            if (lane >= o) w += t;
        }
        wsum[lane] = w;
    }
    __syncthreads();
    int excl = incl - v + (warp ? wsum[warp - 1] : 0) + g_soff[blockIdx.x];
    if (gid < NN) {
        g_rowstart[gid] = excl;
        g_cursor[gid]   = excl;
        g_dinv[gid]     = rsqrtf((float)v + 1.0f);   // + self loop
    }
}

__global__ void fill_k(const int* __restrict__ src, const int* __restrict__ dst) {
    int e = blockIdx.x * blockDim.x + threadIdx.x;
    if (e < EE) {
        int p = atomicAdd(&g_cursor[dst[e]], 1);
        g_adj[p] = src[e];
    }
}

// ---------------------------------------------------------------------------
// tf32 mma.sync GEMM, software-pipelined (2-stage smem double buffer).
// C[M,Nc] = A[M,K] @ W[K,Nc]; BM=128, BN=128, BK=32; 8 warps (2m x 4n).
// STAGE 1: A=g_agg1, C=g_a1 (fp32), Nc=256, K=128, epilogue relu(.+bias)
// STAGE 2: A=g_a1,   C=g_h2h (fp16), Nc=128, K=256, plain
// ---------------------------------------------------------------------------
__device__ __forceinline__ uint32_t f2tf32(float f) {
    uint32_t u;
    asm("cvt.rna.tf32.f32 %0, %1;" : "=r"(u) : "f"(f));
    return u;
}

#define AF_IDX(ks, mt, lane, slot) ((((ks) * 8 + (mt)) * 32 + (lane)) * 4 + (slot))
#define BF_IDX(ks, nt, lane, slot) ((((ks) * 16 + (nt)) * 32 + (lane)) * 2 + (slot))
#define STAGE_U32 8192   // 4096 u32 Af + 4096 u32 Bf per stage

template <int STAGE>
__global__ void __launch_bounds__(256) gemm_mma_k(const float* __restrict__ W,
                                                  const float* __restrict__ bias) {
    constexpr int Nc  = (STAGE == 1) ? F_HID : F_OUT;   // 256 / 128
    constexpr int K   = (STAGE == 1) ? F_IN  : F_HID;   // 128 / 256
    constexpr int NKT = K / 32;

    const float* __restrict__ A = (STAGE == 1) ? g_agg1 : g_a1;

    extern __shared__ uint32_t dsm[];   // 2 stages x (Af 16KB + Bf 16KB)

    const int tid  = threadIdx.x;
    const int wid  = tid >> 5;
    const int lane = tid & 31;
    const int warp_m = wid >> 2;            // 0..1  (64 rows)
    const int warp_n = wid & 3;             // 0..3  (32 cols)
    const int bm = blockIdx.y * 128;
    const int bn = blockIdx.x * 128;

    float c[4][4][4];
    #pragma unroll
    for (int i = 0; i < 4; i++)
        #pragma unroll
        for (int j = 0; j < 4; j++)
            #pragma unroll
            for (int q = 0; q < 4; q++) c[i][j][q] = 0.f;

    // loader coordinates
    const int ar  = tid >> 1;               // A row 0..127
    const int akc = (tid & 1) * 16;         // A col base 0/16
    const int bkr = tid >> 3;               // B k-row 0..31
    const int bnb = (tid & 7) * 16;         // B n base
    const int gr  = bm + ar;
    const bool arow_ok = (gr < NN);

    const int a_mt   = ar >> 4;
    const int a_lb   = (ar & 7) * 4;
    const int a_shi  = ((ar & 15) >= 8) ? 1 : 0;
    const int b_ks   = bkr >> 3;
    const int b_kk   = bkr & 7;
    const int b_slot = b_kk >> 2;
    const int b_kl   = b_kk & 3;

    float4 rA[4], rB[4];

    auto ldg_tile = [&](int kt) {
        const int k0 = kt * 32;
        const float* ap = &A[(size_t)gr * K + k0 + akc];
        #pragma unroll
        for (int i = 0; i < 4; i++)
            rA[i] = arow_ok ? *(const float4*)(ap + 4 * i)
                            : make_float4(0.f, 0.f, 0.f, 0.f);
        const float* bp = &W[(size_t)(k0 + bkr) * Nc + bn + bnb];
        #pragma unroll
        for (int i = 0; i < 4; i++)
            rB[i] = *(const float4*)(bp + 4 * i);
    };

    auto sts_tile = [&](uint32_t* buf) {
        uint32_t* Afb = buf;
        uint32_t* Bfb = buf + 4096;
        #pragma unroll
        for (int i = 0; i < 4; i++) {
            int kc = akc + 4 * i;
            int ks = kc >> 3;
            int aslot = ((kc & 7) >= 4 ? 2 : 0) + a_shi;
            Afb[AF_IDX(ks, a_mt, a_lb + 0, aslot)] = f2tf32(rA[i].x);
            Afb[AF_IDX(ks, a_mt, a_lb + 1, aslot)] = f2tf32(rA[i].y);
            Afb[AF_IDX(ks, a_mt, a_lb + 2, aslot)] = f2tf32(rA[i].z);
            Afb[AF_IDX(ks, a_mt, a_lb + 3, aslot)] = f2tf32(rA[i].w);
        }
        #pragma unroll
        for (int i = 0; i < 4; i++) {
            int nb = bnb + 4 * i;
            int nt = nb >> 3;
            int nn = nb & 7;
            Bfb[BF_IDX(b_ks, nt, (nn + 0) * 4 + b_kl, b_slot)] = f2tf32(rB[i].x);
            Bfb[BF_IDX(b_ks, nt, (nn + 1) * 4 + b_kl, b_slot)] = f2tf32(rB[i].y);
            Bfb[BF_IDX(b_ks, nt, (nn + 2) * 4 + b_kl, b_slot)] = f2tf32(rB[i].z);
            Bfb[BF_IDX(b_ks, nt, (nn + 3) * 4 + b_kl, b_slot)] = f2tf32(rB[i].w);
        }
    };

    ldg_tile(0);

    for (int kt = 0; kt < NKT; kt++) {
        uint32_t* buf = dsm + (kt & 1) * STAGE_U32;
        sts_tile(buf);
        __syncthreads();
        if (kt + 1 < NKT) ldg_tile(kt + 1);

        const uint32_t* Afb = buf;
        const uint32_t* Bfb = buf + 4096;
        #pragma unroll
        for (int ks = 0; ks < 4; ks++) {
            uint32_t a[4][4], b[4][2];
            #pragma unroll
            for (int mt = 0; mt < 4; mt++) {
                uint4 av = *(const uint4*)&Afb[AF_IDX(ks, warp_m * 4 + mt, lane, 0)];
                a[mt][0] = av.x; a[mt][1] = av.y; a[mt][2] = av.z; a[mt][3] = av.w;
            }
            #pragma unroll
            for (int nt = 0; nt < 4; nt++) {
                uint2 bv = *(const uint2*)&Bfb[BF_IDX(ks, warp_n * 4 + nt, lane, 0)];
                b[nt][0] = bv.x; b[nt][1] = bv.y;
            }
            #pragma unroll
            for (int mt = 0; mt < 4; mt++)
                #pragma unroll
                for (int nt = 0; nt < 4; nt++)
                    asm volatile(
                        "mma.sync.aligned.m16n8k8.row.col.f32.tf32.tf32.f32 "
                        "{%0,%1,%2,%3}, {%4,%5,%6,%7}, {%8,%9}, {%0,%1,%2,%3};"
                        : "+f"(c[mt][nt][0]), "+f"(c[mt][nt][1]),
                          "+f"(c[mt][nt][2]), "+f"(c[mt][nt][3])
                        : "r"(a[mt][0]), "r"(a[mt][1]), "r"(a[mt][2]), "r"(a[mt][3]),
                          "r"(b[nt][0]), "r"(b[nt][1]));
        }
    }

    // ---- epilogue ----
    #pragma unroll
    for (int mt = 0; mt < 4; mt++) {
        int row0 = bm + warp_m * 64 + mt * 16 + (lane >> 2);
        #pragma unroll
        for (int nt = 0; nt < 4; nt++) {
            int col = bn + warp_n * 32 + nt * 8 + (lane & 3) * 2;
            float2 lo = make_float2(c[mt][nt][0], c[mt][nt][1]);
            float2 hi = make_float2(c[mt][nt][2], c[mt][nt][3]);
            if (STAGE == 1) {
                float2 bv = *(const float2*)&bias[col];
                lo.x = fmaxf(lo.x + bv.x, 0.f);  lo.y = fmaxf(lo.y + bv.y, 0.f);
                hi.x = fmaxf(hi.x + bv.x, 0.f);  hi.y = fmaxf(hi.y + bv.y, 0.f);
                if (row0 < NN)     *(float2*)&g_a1[(size_t)row0 * Nc + col]       = lo;
                if (row0 + 8 < NN) *(float2*)&g_a1[(size_t)(row0 + 8) * Nc + col] = hi;
            } else {
                if (row0 < NN)
                    *(__half2*)&g_h2h[(size_t)row0 * Nc + col]       = __float22half2_rn(lo);
                if (row0 + 8 < NN)
                    *(__half2*)&g_h2h[(size_t)(row0 + 8) * Nc + col] = __float22half2_rn(hi);
            }
        }
    }
}

// ---------------------------------------------------------------------------
// CSR gather over fp16 rows (F=128 -> 64 half2 per row), warp per node.
// Lane t handles half2 pair {2t, 2t+1} twice (cols 4t..4t+3 as two half2).
// STAGE 1: h = g_xh,  out = g_agg1 (fp32), no bias/relu.
// STAGE 2: h = g_h2h, out = d_out (fp32),  bias+relu.
// ---------------------------------------------------------------------------
template <int STAGE>
__global__ void gather_k(float* __restrict__ oext, const float* __restrict__ bias) {
    const __half2* __restrict__ h2p = (STAGE == 1) ? (const __half2*)g_xh
                                                   : (const __half2*)g_h2h;
    float4* __restrict__ out4 = (STAGE == 1) ? (float4*)g_agg1 : (float4*)oext;

    int warp = (blockIdx.x << 3) | (threadIdx.x >> 5);
    int t    = threadIdx.x & 31;      // handles cols [4t, 4t+4)
    if (warp >= NN) return;
    int d = warp;

    float di = g_dinv[d];
    // self-loop
    uint2 hr = *(const uint2*)&h2p[(size_t)d * 64 + 2 * t];
    float2 p0 = __half22float2(*(__half2*)&hr.x);
    float2 p1 = __half22float2(*(__half2*)&hr.y);
    float4 acc = make_float4(di * p0.x, di * p0.y, di * p1.x, di * p1.y);

    int j   = g_rowstart[d];
    int end = g_rowstart[d + 1];
    int s_next = (j < end) ? g_adj[j] : 0;
    while (j < end) {
        int s = s_next;
        float w = g_dinv[s];
        j++;
        if (j < end) s_next = g_adj[j];
        uint2 hv = *(const uint2*)&h2p[(size_t)s * 64 + 2 * t];
        float2 q0 = __half22float2(*(__half2*)&hv.x);
        float2 q1 = __half22float2(*(__half2*)&hv.y);
        acc.x += w * q0.x;
        acc.y += w * q0.y;
        acc.z += w * q1.x;
        acc.w += w * q1.y;
    }

    float4 v;
    if (STAGE == 2) {
        float4 b4 = ((const float4*)bias)[t];
        v.x = fmaxf(di * acc.x + b4.x, 0.f);
        v.y = fmaxf(di * acc.y + b4.y, 0.f);
        v.z = fmaxf(di * acc.z + b4.z, 0.f);
        v.w = fmaxf(di * acc.w + b4.w, 0.f);
    } else {
        v = make_float4(di * acc.x, di * acc.y, di * acc.z, di * acc.w);
    }
    out4[(size_t)d * 32 + t] = v;
}

// ---------------------------------------------------------------------------
extern "C" void kernel_launch(void* const* d_in, const int* in_sizes, int n_in,
                              void* d_out, int out_size) {
    const float* x  = (const float*)d_in[0];
    const int*   ei = (const int*)d_in[1];   // [2, E] int32 (JAX x64 disabled)
    const float* W1 = (const float*)d_in[2];
    const float* b1 = (const float*)d_in[3];
    const float* W2 = (const float*)d_in[4];
    const float* b2 = (const float*)d_in[5];
    float*       out = (float*)d_out;

    const int* src = ei;
    const int* dst = ei + EE;

    const int T = 256;
    const int GEMM_SMEM = 2 * STAGE_U32 * 4;   // 65536 bytes

    cudaFuncSetAttribute(gemm_mma_k<1>, cudaFuncAttributeMaxDynamicSharedMemorySize, GEMM_SMEM);
    cudaFuncSetAttribute(gemm_mma_k<2>, cudaFuncAttributeMaxDynamicSharedMemorySize, GEMM_SMEM);

    // CSR build + normalization + fp16 conversion of x
    zero_cnt_k   <<<(NN + T - 1) / T, T>>>();
    cnt_k        <<<(EE + T - 1) / T, T>>>(dst);
    cvt_x_k      <<<(NN * F_IN / 8 + T - 1) / T, T>>>(x);
    strip_sum_k  <<<NSTRIP, SCAN_T>>>();
    scan_strips_k<<<1, SCAN_T>>>();
    rowstart_k   <<<NSTRIP, SCAN_T>>>();
    fill_k       <<<(EE + T - 1) / T, T>>>(src, dst);

    const int GB = (NN + 7) / 8;          // gather blocks (8 nodes each)
    const int MB = (NN + 127) / 128;      // 391 gemm row-tiles

    // ---- Layer 1:  a1 = relu( (A_norm @ x) @ W1 + b1 ) ----
    gather_k<1><<<GB, 256>>>(nullptr, nullptr);
    gemm_mma_k<1><<<dim3(F_HID / 128, MB), 256, GEMM_SMEM>>>(W1, b1);

    // ---- Layer 2:  out = relu( A_norm @ (a1 @ W2) + b2 ) ----
    gemm_mma_k<2><<<dim3(F_OUT / 128, MB), 256, GEMM_SMEM>>>(W2, nullptr);
    gather_k<2><<<GB, 256>>>(out, b2);
}